// round 15
// baseline (speedup 1.0000x reference)
#include <cuda_runtime.h>
#include <cuda_fp16.h>
#include <cstdint>
#include <cstddef>

typedef unsigned long long u64;
typedef unsigned int u32;

#define N_PTS   65536
#define D_MODEL 256
#define FF_DIM  2048
#define WS      128
#define NH      8
#define DH      32
#define NLAYER  4

// ---------------- scratch ----------------------------------------------------
__device__ u64 g_keysA[N_PTS];
__device__ u64 g_keysB[N_PTS];
__device__ u32 g_hist[256 * 256];
__device__ u32 g_digtot[256];
__device__ u32 g_digbase[256];
__device__ float  g_x   [(size_t)N_PTS * D_MODEL];
__device__ __half g_qkv16[(size_t)N_PTS * 3 * D_MODEL];
__device__ __half g_x16 [(size_t)N_PTS * D_MODEL];
__device__ __half g_att16[(size_t)N_PTS * D_MODEL];
__device__ __half g_ff16[(size_t)N_PTS * FF_DIM];
__device__ __half g_w16 [5242880];

#define WOFF_QKV 0
#define WOFF_O   786432
#define WOFF_1   1048576
#define WOFF_2   3145728

__global__ void cvt_all_kernel(const float* __restrict__ wqkv,
                               const float* __restrict__ wo,
                               const float* __restrict__ w1,
                               const float* __restrict__ w2,
                               __half* __restrict__ out) {
    int i = blockIdx.x * 256 + threadIdx.x;
    float v;
    if (i < 1048576) v = (i < 786432) ? wqkv[i] : wo[i - 786432];
    else             v = (i < 3145728) ? w1[i - 1048576] : w2[i - 3145728];
    out[i] = __float2half_rn(v);
}

// ---------------- morton keys ------------------------------------------------
__global__ void build_keys_kernel(const int* __restrict__ coords, u64* __restrict__ keys) {
    int i = blockIdx.x * 256 + threadIdx.x;
    int b = coords[i * 4 + 0];
    int x = coords[i * 4 + 1];
    int y = coords[i * 4 + 2];
    int z = coords[i * 4 + 3];
    u32 m = 0;
#pragma unroll
    for (int k = 0; k < 7; k++) {
        m |= ((u32)((x >> k) & 1) << (3 * k + 2))
           | ((u32)((y >> k) & 1) << (3 * k + 1))
           | ((u32)((z >> k) & 1) << (3 * k));
    }
    u64 key = ((u64)b << 21) | (u64)m;
    keys[i] = (key << 16) | (u32)i;
}

// ---------------- stable LSD radix sort (parallel bookkeeping) ---------------
__global__ void radix_hist_kernel(const u64* __restrict__ in, int shift) {
    __shared__ u32 h[256];
    int t = threadIdx.x, b = blockIdx.x;
    h[t] = 0;
    __syncthreads();
    u32 d = (u32)((in[b * 256 + t] >> shift) & 0xFF);
    atomicAdd(&h[d], 1u);
    __syncthreads();
    g_hist[b * 256 + t] = h[t];
}

__global__ void radix_colscan_kernel() {
    __shared__ u32 sc[256];
    int d = blockIdx.x;
    int b = threadIdx.x;
    u32 v = g_hist[b * 256 + d];
    sc[b] = v;
    __syncthreads();
#pragma unroll
    for (int off = 1; off < 256; off <<= 1) {
        u32 t = (b >= off) ? sc[b - off] : 0u;
        __syncthreads();
        sc[b] += t;
        __syncthreads();
    }
    g_hist[b * 256 + d] = sc[b] - v;
    if (b == 255) g_digtot[d] = sc[255];
}

__global__ void radix_digbase_kernel() {
    __shared__ u32 sc[256];
    int d = threadIdx.x;
    u32 v = g_digtot[d];
    sc[d] = v;
    __syncthreads();
#pragma unroll
    for (int off = 1; off < 256; off <<= 1) {
        u32 t = (d >= off) ? sc[d - off] : 0u;
        __syncthreads();
        sc[d] += t;
        __syncthreads();
    }
    g_digbase[d] = sc[d] - v;
}

__global__ void radix_scatter_kernel(const u64* __restrict__ in, u64* __restrict__ out, int shift) {
    __shared__ u32 whist[8][256];
    int t = threadIdx.x, b = blockIdx.x;
    int lane = t & 31, wid = t >> 5;

#pragma unroll
    for (int i = 0; i < 8; i++) whist[i][t] = 0;
    __syncthreads();

    u64 key = in[b * 256 + t];
    u32 d = (u32)((key >> shift) & 0xFF);

    u32 mmask = __match_any_sync(0xffffffffu, d);
    u32 lrank = __popc(mmask & ((1u << lane) - 1u));
    if (lrank == 0) whist[wid][d] = __popc(mmask);
    __syncthreads();

    u32 rank = lrank;
#pragma unroll
    for (int w2 = 0; w2 < 8; w2++)
        if (w2 < wid) rank += whist[w2][d];

    out[g_digbase[d] + g_hist[b * 256 + d] + rank] = key;
}

// ---------------- gather + PE ------------------------------------------------
__global__ void gather_pe_kernel(const u64* __restrict__ keys,
                                 const int* __restrict__ coords,
                                 const float* __restrict__ feat,
                                 const float* __restrict__ pex,
                                 const float* __restrict__ pey,
                                 const float* __restrict__ pez,
                                 const float* __restrict__ pes,
                                 float* __restrict__ x,
                                 __half* __restrict__ x16) {
    int i = blockIdx.x;
    int t = threadIdx.x;
    int j = (int)(keys[i] & 0xFFFFu);
    int cx = coords[j * 4 + 1];
    int cy = coords[j * 4 + 2];
    int cz = coords[j * 4 + 3];
    float v = feat[(size_t)j * 256 + t]
            + pex[cx * 256 + t] + pey[cy * 256 + t]
            + pez[cz * 256 + t] + pes[256 + t];
    x[(size_t)i * 256 + t]   = v;
    x16[(size_t)i * 256 + t] = __float2half_rn(v);
}

// ---------------- shared mma helpers ----------------------------------------
__device__ __forceinline__ void cp_async16h(u32 saddr, const void* g) {
    asm volatile("cp.async.cg.shared.global [%0], [%1], 16;" :: "r"(saddr), "l"(g));
}
__device__ __forceinline__ void ldsm4(u32& r0, u32& r1, u32& r2, u32& r3, u32 addr) {
    asm volatile("ldmatrix.sync.aligned.m8n8.x4.shared.b16 {%0,%1,%2,%3}, [%4];"
                 : "=r"(r0), "=r"(r1), "=r"(r2), "=r"(r3) : "r"(addr));
}
__device__ __forceinline__ void mma16816(float* c, const u32* a, const u32* b) {
    asm volatile(
        "mma.sync.aligned.m16n8k16.row.col.f32.f16.f16.f32 "
        "{%0,%1,%2,%3}, {%4,%5,%6,%7}, {%8,%9}, {%0,%1,%2,%3};"
        : "+f"(c[0]), "+f"(c[1]), "+f"(c[2]), "+f"(c[3])
        : "r"(a[0]), "r"(a[1]), "r"(a[2]), "r"(a[3]), "r"(b[0]), "r"(b[1]));
}

// ============ GEMM A: persistent, 128x128x64 tiles, 3-stage continuous ring ==
// CTA bid processes tiles bid, bid+G, ... ; cp.async ring never drains across
// tile boundaries (next tile's stages prefetch while epilogue of prev runs).
#define G6_BM 128
#define G6_BN 128
#define G6_BK 64
#define G6_NSTAGE 3
#define G6_ASTAGE (G6_BM * G6_BK * 2)
#define G6_STAGE  (G6_ASTAGE * 2)
#define G6_SMEM   (G6_NSTAGE * G6_STAGE)
#define G6_GRID   296

__global__ __launch_bounds__(128) void gemm_f16_kernel(
    const __half* __restrict__ A, const __half* __restrict__ B,
    const float* __restrict__ bias, __half* __restrict__ C16,
    int Nn, int K, int mode, int ntiles, int ntn)
{
    extern __shared__ char smem_raw[];
    u32 sbase = (u32)__cvta_generic_to_shared(smem_raw);

    int tid  = threadIdx.x;
    int lane = tid & 31;
    int warp = tid >> 5;
    int wm = warp & 1;
    int wn = warp >> 1;
    int bid = blockIdx.x;
    int G   = gridDim.x;

    const int KT = K / G6_BK;
    int nmyt = (ntiles - bid + G - 1) / G;
    if (nmyt <= 0) return;
    int mytotal = nmyt * KT;

    // load global-iteration j (stage j%3): tile = bid + (j/KT)*G, kt = j%KT
    auto load_g = [&](int j) {
        if (j < mytotal) {
            int t  = bid + (j / KT) * G;
            int kt = j % KT;
            int m0 = (t / ntn) * G6_BM;
            int n0 = (t % ntn) * G6_BN;
            const __half* Ag = A + (size_t)m0 * K;
            const __half* Bg = B + (size_t)n0 * K;
            int k0 = kt * G6_BK;
            u32 sa = sbase + (u32)(j % G6_NSTAGE) * G6_STAGE;
            u32 sb = sa + G6_ASTAGE;
#pragma unroll
            for (int i = 0; i < 8; i++) {
                int q = tid + i * 128;
                int r = q >> 3, ch = q & 7;
                u32 off = (u32)(r * 8 + (ch ^ (r & 7))) * 16u;
                cp_async16h(sa + off, Ag + (size_t)r * K + k0 + ch * 8);
                cp_async16h(sb + off, Bg + (size_t)r * K + k0 + ch * 8);
            }
        }
        asm volatile("cp.async.commit_group;");
    };

    load_g(0);
    load_g(1);

    int idx  = lane >> 3;
    int lrow = lane & 7;
    int a_mo = (idx & 1) * 8;
    int a_kc = idx >> 1;
    int b_no = (idx >> 1) * 8;
    int b_kc = idx & 1;

    float c[4][8][4];
#pragma unroll
    for (int i = 0; i < 4; i++)
#pragma unroll
        for (int j2 = 0; j2 < 8; j2++)
#pragma unroll
            for (int k2 = 0; k2 < 4; k2++) c[i][j2][k2] = 0.f;

    for (int j = 0; j < mytotal; j++) {
        asm volatile("cp.async.wait_group 1;");
        __syncthreads();
        load_g(j + 2);

        u32 sa = sbase + (u32)(j % G6_NSTAGE) * G6_STAGE;
        u32 sb = sa + G6_ASTAGE;

#pragma unroll
        for (int ks = 0; ks < 4; ks++) {
            u32 a[4][4];
#pragma unroll
            for (int mt = 0; mt < 4; mt++) {
                int r  = wm * 64 + mt * 16 + a_mo + lrow;
                int ch = ks * 2 + a_kc;
                ldsm4(a[mt][0], a[mt][1], a[mt][2], a[mt][3],
                      sa + (u32)(r * 8 + (ch ^ (r & 7))) * 16u);
            }
            u32 b[8][2];
#pragma unroll
            for (int nt2 = 0; nt2 < 4; nt2++) {
                int r  = wn * 64 + nt2 * 16 + b_no + lrow;
                int ch = ks * 2 + b_kc;
                u32 t0, t1, t2, t3;
                ldsm4(t0, t1, t2, t3, sb + (u32)(r * 8 + (ch ^ (r & 7))) * 16u);
                b[nt2 * 2][0] = t0; b[nt2 * 2][1] = t1;
                b[nt2 * 2 + 1][0] = t2; b[nt2 * 2 + 1][1] = t3;
            }
#pragma unroll
            for (int mt = 0; mt < 4; mt++)
#pragma unroll
                for (int nt = 0; nt < 8; nt++)
                    mma16816(c[mt][nt], a[mt], b[nt]);
        }
        __syncthreads();

        if ((j % KT) == KT - 1) {
            // epilogue for tile just finished (loads for next tile in flight)
            int t  = bid + (j / KT) * G;
            int m0 = (t / ntn) * G6_BM;
            int n0 = (t % ntn) * G6_BN;
#pragma unroll
            for (int mt = 0; mt < 4; mt++) {
#pragma unroll
                for (int nt = 0; nt < 8; nt++) {
                    int row = m0 + wm * 64 + mt * 16 + (lane >> 2);
                    int col = n0 + wn * 64 + nt * 8 + (lane & 3) * 2;
                    float2 bv = *(const float2*)(bias + col);
                    float v0 = c[mt][nt][0] + bv.x;
                    float v1 = c[mt][nt][1] + bv.y;
                    float v2 = c[mt][nt][2] + bv.x;
                    float v3 = c[mt][nt][3] + bv.y;
                    if (mode == 2) {
                        v0 = fmaxf(v0, 0.f); v1 = fmaxf(v1, 0.f);
                        v2 = fmaxf(v2, 0.f); v3 = fmaxf(v3, 0.f);
                    }
                    *(__half2*)(C16 + (size_t)row * Nn + col) = __floats2half2_rn(v0, v1);
                    *(__half2*)(C16 + (size_t)(row + 8) * Nn + col) = __floats2half2_rn(v2, v3);
                    c[mt][nt][0] = 0.f; c[mt][nt][1] = 0.f;
                    c[mt][nt][2] = 0.f; c[mt][nt][3] = 0.f;
                }
            }
        }
    }
}

// ============ GEMM B: 128x256x64, 2-stage, fused residual + LayerNorm ========
#define GL_BM 128
#define GL_BN 256
#define GL_BK 64
#define GL_ASTAGE (GL_BM * GL_BK * 2)
#define GL_BSTAGE (GL_BN * GL_BK * 2)
#define GL_STAGE  (GL_ASTAGE + GL_BSTAGE)
#define GL_SMEM   (2 * GL_STAGE)

__global__ __launch_bounds__(256) void gemm_ln_kernel(
    const __half* __restrict__ A, const __half* __restrict__ B,
    const float* __restrict__ bias,
    __half* __restrict__ C16, float* __restrict__ C32,
    const float* __restrict__ resid,
    const float* __restrict__ gamma, const float* __restrict__ beta,
    int K)
{
    extern __shared__ char smem_raw[];
    u32 sbase = (u32)__cvta_generic_to_shared(smem_raw);

    int tid  = threadIdx.x;
    int lane = tid & 31;
    int warp = tid >> 5;
    int wm = warp & 1;
    int wn = warp >> 1;
    int m0 = blockIdx.y * GL_BM;

    const __half* Ag = A + (size_t)m0 * K;
    const __half* Bg = B;

    float c[4][8][4];
#pragma unroll
    for (int i = 0; i < 4; i++)
#pragma unroll
        for (int j = 0; j < 8; j++)
#pragma unroll
            for (int k = 0; k < 4; k++) c[i][j][k] = 0.f;

    const int KT = K / GL_BK;

    auto load_stage = [&](int tile) {
        if (tile < KT) {
            int k0 = tile * GL_BK;
            u32 sa = sbase + (u32)(tile & 1) * GL_STAGE;
            u32 sb = sa + GL_ASTAGE;
#pragma unroll
            for (int i = 0; i < 4; i++) {
                int q = tid + i * 256;
                int r = q >> 3, ch = q & 7;
                u32 off = (u32)(r * 8 + (ch ^ (r & 7))) * 16u;
                cp_async16h(sa + off, Ag + (size_t)r * K + k0 + ch * 8);
            }
#pragma unroll
            for (int i = 0; i < 8; i++) {
                int q = tid + i * 256;
                int r = q >> 3, ch = q & 7;
                u32 off = (u32)(r * 8 + (ch ^ (r & 7))) * 16u;
                cp_async16h(sb + off, Bg + (size_t)r * K + k0 + ch * 8);
            }
        }
        asm volatile("cp.async.commit_group;");
    };

    load_stage(0);
    load_stage(1);

    int idx  = lane >> 3;
    int lrow = lane & 7;
    int a_mo = (idx & 1) * 8;
    int a_kc = idx >> 1;
    int b_no = (idx >> 1) * 8;
    int b_kc = idx & 1;

    for (int kt = 0; kt < KT; kt++) {
        asm volatile("cp.async.wait_group 1;");
        __syncthreads();

        u32 sa = sbase + (u32)(kt & 1) * GL_STAGE;
        u32 sb = sa + GL_ASTAGE;

#pragma unroll
        for (int ks = 0; ks < 4; ks++) {
            u32 a[4][4];
#pragma unroll
            for (int mt = 0; mt < 4; mt++) {
                int r  = wm * 64 + mt * 16 + a_mo + lrow;
                int ch = ks * 2 + a_kc;
                ldsm4(a[mt][0], a[mt][1], a[mt][2], a[mt][3],
                      sa + (u32)(r * 8 + (ch ^ (r & 7))) * 16u);
            }
            u32 b[8][2];
#pragma unroll
            for (int nt2 = 0; nt2 < 4; nt2++) {
                int r  = wn * 64 + nt2 * 16 + b_no + lrow;
                int ch = ks * 2 + b_kc;
                u32 t0, t1, t2, t3;
                ldsm4(t0, t1, t2, t3, sb + (u32)(r * 8 + (ch ^ (r & 7))) * 16u);
                b[nt2 * 2][0] = t0; b[nt2 * 2][1] = t1;
                b[nt2 * 2 + 1][0] = t2; b[nt2 * 2 + 1][1] = t3;
            }
#pragma unroll
            for (int mt = 0; mt < 4; mt++)
#pragma unroll
                for (int nt = 0; nt < 8; nt++)
                    mma16816(c[mt][nt], a[mt], b[nt]);
        }
        __syncthreads();
        load_stage(kt + 2);
    }

    asm volatile("cp.async.wait_group 0;");
    __syncthreads();

    float2 bv[8];
#pragma unroll
    for (int nt = 0; nt < 8; nt++)
        bv[nt] = *(const float2*)(bias + wn * 64 + nt * 8 + (lane & 3) * 2);

    float* red = (float*)smem_raw;

#pragma unroll
    for (int mt = 0; mt < 4; mt++) {
#pragma unroll
        for (int rh = 0; rh < 2; rh++) {
            int rowl = wm * 64 + mt * 16 + (lane >> 2) + rh * 8;
            const float* rrow = resid + (size_t)(m0 + rowl) * 256 + wn * 64 + (lane & 3) * 2;
            float s = 0.f, s2 = 0.f;
#pragma unroll
            for (int nt = 0; nt < 8; nt++) {
                float2 rv = *(const float2*)(rrow + nt * 8);
                float v0 = c[mt][nt][rh * 2]     + bv[nt].x + rv.x;
                float v1 = c[mt][nt][rh * 2 + 1] + bv[nt].y + rv.y;
                c[mt][nt][rh * 2]     = v0;
                c[mt][nt][rh * 2 + 1] = v1;
                s += v0 + v1;
                s2 = fmaf(v0, v0, s2);
                s2 = fmaf(v1, v1, s2);
            }
            s  += __shfl_xor_sync(0xffffffffu, s, 1);
            s  += __shfl_xor_sync(0xffffffffu, s, 2);
            s2 += __shfl_xor_sync(0xffffffffu, s2, 1);
            s2 += __shfl_xor_sync(0xffffffffu, s2, 2);
            if ((lane & 3) == 0) {
                red[rowl * 8 + wn * 2]     = s;
                red[rowl * 8 + wn * 2 + 1] = s2;
            }
        }
    }
    __syncthreads();

    float2 gv[8], bev[8];
#pragma unroll
    for (int nt = 0; nt < 8; nt++) {
        int col = wn * 64 + nt * 8 + (lane & 3) * 2;
        gv[nt]  = *(const float2*)(gamma + col);
        bev[nt] = *(const float2*)(beta + col);
    }

#pragma unroll
    for (int mt = 0; mt < 4; mt++) {
#pragma unroll
        for (int rh = 0; rh < 2; rh++) {
            int rowl = wm * 64 + mt * 16 + (lane >> 2) + rh * 8;
            float s  = red[rowl * 8 + 0] + red[rowl * 8 + 2] + red[rowl * 8 + 4] + red[rowl * 8 + 6];
            float s2 = red[rowl * 8 + 1] + red[rowl * 8 + 3] + red[rowl * 8 + 5] + red[rowl * 8 + 7];
            float mean = s * (1.f / 256.f);
            float var  = s2 * (1.f / 256.f) - mean * mean;
            float rstd = rsqrtf(var + 1e-5f);
            int row = m0 + rowl;
            float*  o32 = C32 + (size_t)row * 256 + wn * 64 + (lane & 3) * 2;
            __half* o16 = C16 + (size_t)row * 256 + wn * 64 + (lane & 3) * 2;
#pragma unroll
            for (int nt = 0; nt < 8; nt++) {
                float v0 = (c[mt][nt][rh * 2]     - mean) * rstd * gv[nt].x + bev[nt].x;
                float v1 = (c[mt][nt][rh * 2 + 1] - mean) * rstd * gv[nt].y + bev[nt].y;
                float2 o = {v0, v1};
                *(float2*)(o32 + nt * 8) = o;
                *(__half2*)(o16 + nt * 8) = __floats2half2_rn(v0, v1);
            }
        }
    }
}

// ---------------- flash attention: mma + f16x2 exp, no running max -----------
#define QK_STRB 80
#define VT_STRB 272
__device__ __forceinline__ u32 h2ex2(u32 x) {
    u32 r;
    asm volatile("ex2.approx.f16x2 %0, %1;" : "=r"(r) : "r"(x));
    return r;
}
__device__ __forceinline__ u32 packh2(float a, float b) {
    __half2 h = __floats2half2_rn(a, b);
    return *(u32*)&h;
}

__global__ __launch_bounds__(128) void attn_mma_kernel(const __half* __restrict__ qkv,
                                                       __half* __restrict__ att16) {
    __shared__ __align__(16) __half Qs[128 * 40];
    __shared__ __align__(16) __half Ks[128 * 40];
    __shared__ __align__(16) __half Vt[32 * 136];

    int w = blockIdx.x;
    int h = blockIdx.y;
    int p = threadIdx.x;
    int lane = p & 31;
    int warp = p >> 5;

    {
        const __half* base = qkv + ((size_t)w * WS + p) * 768 + h * 32;
        const uint4* q4 = (const uint4*)base;
        const uint4* k4 = (const uint4*)(base + 256);
        const uint4* v4 = (const uint4*)(base + 512);
        uint4* qd = (uint4*)(Qs + p * 40);
        uint4* kd = (uint4*)(Ks + p * 40);
#pragma unroll
        for (int c = 0; c < 4; c++) { qd[c] = q4[c]; kd[c] = k4[c]; }
        union { uint4 u[4]; __half hh[32]; } vv;
#pragma unroll
        for (int c = 0; c < 4; c++) vv.u[c] = v4[c];
#pragma unroll
        for (int d = 0; d < 32; d++) Vt[d * 136 + p] = vv.hh[d];
    }
    __syncthreads();

    u32 qsb = (u32)__cvta_generic_to_shared(Qs);
    u32 ksb = (u32)__cvta_generic_to_shared(Ks);
    u32 vtb = (u32)__cvta_generic_to_shared(Vt);

    int idx  = lane >> 3;
    int lrow = lane & 7;
    int a_mo = (idx & 1) * 8;
    int a_kc = idx >> 1;
    int b_no = (idx >> 1) * 8;
    int b_kc = idx & 1;
    int m_base = warp * 32;

    const float scale = 0.2550540263f;  // log2(e)/sqrt(32)

    float lrow_s[2][2];
    float o[2][4][4];
#pragma unroll
    for (int t = 0; t < 2; t++)
#pragma unroll
        for (int rh = 0; rh < 2; rh++) lrow_s[t][rh] = 0.f;
#pragma unroll
    for (int t = 0; t < 2; t++)
#pragma unroll
        for (int n = 0; n < 4; n++)
#pragma unroll
            for (int k = 0; k < 4; k++) o[t][n][k] = 0.f;

#pragma unroll
    for (int chunk = 0; chunk < 2; chunk++) {
        int n0c = chunk * 64;

        float s[2][8][4];
#pragma unroll
        for (int t = 0; t < 2; t++)
#pragma unroll
            for (int n = 0; n < 8; n++)
#pragma unroll
                for (int k = 0; k < 4; k++) s[t][n][k] = 0.f;

#pragma unroll
        for (int ks = 0; ks < 2; ks++) {
            u32 a[2][4];
#pragma unroll
            for (int t = 0; t < 2; t++) {
                int r  = m_base + t * 16 + a_mo + lrow;
                int ch = ks * 2 + a_kc;
                ldsm4(a[t][0], a[t][1], a[t][2], a[t][3],
                      qsb + (u32)(r * QK_STRB + ch * 16));
            }
            u32 b[8][2];
#pragma unroll
            for (int np = 0; np < 4; np++) {
                int r  = n0c + np * 16 + b_no + lrow;
                int ch = ks * 2 + b_kc;
                u32 t0, t1, t2, t3;
                ldsm4(t0, t1, t2, t3, ksb + (u32)(r * QK_STRB + ch * 16));
                b[np * 2][0] = t0; b[np * 2][1] = t1;
                b[np * 2 + 1][0] = t2; b[np * 2 + 1][1] = t3;
            }
#pragma unroll
            for (int t = 0; t < 2; t++)
#pragma unroll
                for (int n = 0; n < 8; n++)
                    mma16816(s[t][n], a[t], b[n]);
        }

        u32 pf_lo[2][8], pf_hi[2][8];
#pragma unroll
        for (int t = 0; t < 2; t++) {
#pragma unroll
            for (int rh = 0; rh < 2; rh++) {
                float lsum = 0.f;
#pragma unroll
                for (int n = 0; n < 8; n++) {
                    float v0 = s[t][n][rh * 2]     * scale;
                    float v1 = s[t][n][rh * 2 + 1] * scale;
                    u32 pp = h2ex2(packh2(v0, v1));
                    if (rh == 0) pf_lo[t][n] = pp; else pf_hi[t][n] = pp;
                    __half2 ph = *(__half2*)&pp;
                    float2 pfv = __half22float2(ph);
                    lsum += pfv.x + pfv.y;
                }
                lrow_s[t][rh] += lsum;
            }
        }

#pragma unroll
        for (int ks2 = 0; ks2 < 4; ks2++) {
            u32 b[4][2];
#pragma unroll
            for (int np = 0; np < 2; np++) {
                int r = np * 16 + b_no + lrow;
                int kh = n0c + ks2 * 16 + b_kc * 8;
                u32 t0, t1, t2, t3;
                ldsm4(t0, t1, t2, t3, vtb + (u32)(r * VT_STRB + kh * 2));
                b[np * 2][0] = t0; b[np * 2][1] = t1;
                b[np * 2 + 1][0] = t2; b[np * 2 + 1][1] = t3;
            }
#pragma unroll
            for (int t = 0; t < 2; t++) {
                u32 a[4];
                a[0] = pf_lo[t][ks2 * 2];
                a[1] = pf_hi[t][ks2 * 2];
                a[2] = pf_lo[t][ks2 * 2 + 1];
                a[3] = pf_hi[t][ks2 * 2 + 1];
#pragma unroll
                for (int n = 0; n < 4; n++)
                    mma16816(o[t][n], a, b[n]);
            }
        }
    }

#pragma unroll
    for (int t = 0; t < 2; t++) {
#pragma unroll
        for (int rh = 0; rh < 2; rh++) {
            float lr = lrow_s[t][rh];
            lr += __shfl_xor_sync(0xffffffffu, lr, 1);
            lr += __shfl_xor_sync(0xffffffffu, lr, 2);
            float inv = 1.f / lr;
            int row = w * WS + m_base + t * 16 + (lane >> 2) + rh * 8;
            __half* outp = att16 + (size_t)row * 256 + h * 32 + (lane & 3) * 2;
#pragma unroll
            for (int n = 0; n < 4; n++) {
                *(__half2*)(outp + n * 8) =
                    __floats2half2_rn(o[t][n][rh * 2] * inv, o[t][n][rh * 2 + 1] * inv);
            }
        }
    }
}

// ---------------- launch ------------------------------------------------------
extern "C" void kernel_launch(void* const* d_in, const int* in_sizes, int n_in,
                              void* d_out, int out_size) {
    const int*   coords = (const int*)d_in[0];
    const float* feat   = (const float*)d_in[1];
    const float* pex    = (const float*)d_in[2];
    const float* pey    = (const float*)d_in[3];
    const float* pez    = (const float*)d_in[4];
    const float* pes    = (const float*)d_in[5];
    const float* Wqkv   = (const float*)d_in[6];
    const float* bqkv   = (const float*)d_in[7];
    const float* Wo     = (const float*)d_in[8];
    const float* bo     = (const float*)d_in[9];
    const float* W1     = (const float*)d_in[10];
    const float* b1     = (const float*)d_in[11];
    const float* W2     = (const float*)d_in[12];
    const float* b2     = (const float*)d_in[13];
    const float* g1     = (const float*)d_in[14];
    const float* be1    = (const float*)d_in[15];
    const float* g2     = (const float*)d_in[16];
    const float* be2    = (const float*)d_in[17];

    u64 *ka, *kb;
    float *xp;
    __half *qkv16p, *x16p, *att16p, *ff16p, *w16p;
    cudaGetSymbolAddress((void**)&ka,     g_keysA);
    cudaGetSymbolAddress((void**)&kb,     g_keysB);
    cudaGetSymbolAddress((void**)&xp,     g_x);
    cudaGetSymbolAddress((void**)&qkv16p, g_qkv16);
    cudaGetSymbolAddress((void**)&x16p,   g_x16);
    cudaGetSymbolAddress((void**)&att16p, g_att16);
    cudaGetSymbolAddress((void**)&ff16p,  g_ff16);
    cudaGetSymbolAddress((void**)&w16p,   g_w16);

    static int attr_done = 0;
    if (!attr_done) {
        cudaFuncSetAttribute(gemm_f16_kernel,
                             cudaFuncAttributeMaxDynamicSharedMemorySize, G6_SMEM);
        cudaFuncSetAttribute(gemm_ln_kernel,
                             cudaFuncAttributeMaxDynamicSharedMemorySize, GL_SMEM);
        attr_done = 1;
    }

    // 0) weights -> fp16
    cvt_all_kernel<<<5242880 / 256, 256>>>(Wqkv, Wo, W1, W2, w16p);

    // 1) sort
    build_keys_kernel<<<256, 256>>>(coords, ka);
    int shifts[3] = {16, 24, 32};
    u64* src = ka;
    u64* dst = kb;
    for (int p = 0; p < 3; p++) {
        radix_hist_kernel<<<256, 256>>>(src, shifts[p]);
        radix_colscan_kernel<<<256, 256>>>();
        radix_digbase_kernel<<<1, 256>>>();
        radix_scatter_kernel<<<256, 256>>>(src, dst, shifts[p]);
        u64* t = src; src = dst; dst = t;
    }

    // 2) gather + PE
    gather_pe_kernel<<<N_PTS, 256>>>(src, coords, feat, pex, pey, pez, pes, xp, x16p);

    // 3) layers
    const int QKV_NTN = 768 / G6_BN;                       // 6
    const int QKV_NT  = (N_PTS / G6_BM) * QKV_NTN;         // 3072
    const int FF1_NTN = 2048 / G6_BN;                      // 16
    const int FF1_NT  = (N_PTS / G6_BM) * FF1_NTN;         // 8192

    for (int l = 0; l < NLAYER; l++) {
        const __half* wqkv = w16p + WOFF_QKV + (size_t)l * 768 * 256;
        const float*  bq   = bqkv + (size_t)l * 768;
        const __half* wo   = w16p + WOFF_O + (size_t)l * 256 * 256;
        const float*  bo_l = bo   + (size_t)l * 256;
        const __half* w1   = w16p + WOFF_1 + (size_t)l * 2048 * 256;
        const float*  b1_l = b1   + (size_t)l * 2048;
        const __half* w2   = w16p + WOFF_2 + (size_t)l * 256 * 2048;
        const float*  b2_l = b2   + (size_t)l * 256;

        gemm_f16_kernel<<<G6_GRID, 128, G6_SMEM>>>(
            x16p, wqkv, bq, qkv16p, 768, 256, 1, QKV_NT, QKV_NTN);

        attn_mma_kernel<<<dim3(N_PTS / WS, NH), 128>>>(qkv16p, att16p);

        gemm_ln_kernel<<<dim3(1, N_PTS / GL_BM), 256, GL_SMEM>>>(
            att16p, wo, bo_l, x16p, xp, xp, g1 + l * 256, be1 + l * 256, 256);

        gemm_f16_kernel<<<G6_GRID, 128, G6_SMEM>>>(
            x16p, w1, b1_l, ff16p, 2048, 256, 2, FF1_NT, FF1_NTN);

        float* outp = (l == NLAYER - 1) ? (float*)d_out : xp;
        gemm_ln_kernel<<<dim3(1, N_PTS / GL_BM), 256, GL_SMEM>>>(
            ff16p, w2, b2_l, x16p, outp, xp, g2 + l * 256, be2 + l * 256, 2048);
    }
}

// round 16
// speedup vs baseline: 1.0692x; 1.0692x over previous
#include <cuda_runtime.h>
#include <cuda_fp16.h>
#include <cstdint>
#include <cstddef>

typedef unsigned long long u64;
typedef unsigned int u32;

#define N_PTS   65536
#define D_MODEL 256
#define FF_DIM  2048
#define WS      128
#define NH      8
#define DH      32
#define NLAYER  4

// ---------------- scratch ----------------------------------------------------
__device__ u64 g_keysA[N_PTS];
__device__ u64 g_keysB[N_PTS];
__device__ u32 g_hist[256 * 256];
__device__ u32 g_digtot[256];
__device__ u32 g_digbase[256];
__device__ float  g_x   [(size_t)N_PTS * D_MODEL];
__device__ __half g_qkv16[(size_t)N_PTS * 3 * D_MODEL];
__device__ __half g_x16 [(size_t)N_PTS * D_MODEL];
__device__ __half g_att16[(size_t)N_PTS * D_MODEL];
__device__ __half g_ff16[(size_t)N_PTS * FF_DIM];
__device__ __half g_w16 [5242880];

#define WOFF_QKV 0
#define WOFF_O   786432
#define WOFF_1   1048576
#define WOFF_2   3145728

__global__ void cvt_all_kernel(const float* __restrict__ wqkv,
                               const float* __restrict__ wo,
                               const float* __restrict__ w1,
                               const float* __restrict__ w2,
                               __half* __restrict__ out) {
    int i = blockIdx.x * 256 + threadIdx.x;
    float v;
    if (i < 1048576) v = (i < 786432) ? wqkv[i] : wo[i - 786432];
    else             v = (i < 3145728) ? w1[i - 1048576] : w2[i - 3145728];
    out[i] = __float2half_rn(v);
}

// ---------------- morton keys ------------------------------------------------
__global__ void build_keys_kernel(const int* __restrict__ coords, u64* __restrict__ keys) {
    int i = blockIdx.x * 256 + threadIdx.x;
    int b = coords[i * 4 + 0];
    int x = coords[i * 4 + 1];
    int y = coords[i * 4 + 2];
    int z = coords[i * 4 + 3];
    u32 m = 0;
#pragma unroll
    for (int k = 0; k < 7; k++) {
        m |= ((u32)((x >> k) & 1) << (3 * k + 2))
           | ((u32)((y >> k) & 1) << (3 * k + 1))
           | ((u32)((z >> k) & 1) << (3 * k));
    }
    u64 key = ((u64)b << 21) | (u64)m;
    keys[i] = (key << 16) | (u32)i;
}

// ---------------- stable LSD radix sort (parallel bookkeeping) ---------------
__global__ void radix_hist_kernel(const u64* __restrict__ in, int shift) {
    __shared__ u32 h[256];
    int t = threadIdx.x, b = blockIdx.x;
    h[t] = 0;
    __syncthreads();
    u32 d = (u32)((in[b * 256 + t] >> shift) & 0xFF);
    atomicAdd(&h[d], 1u);
    __syncthreads();
    g_hist[b * 256 + t] = h[t];
}

__global__ void radix_colscan_kernel() {
    __shared__ u32 sc[256];
    int d = blockIdx.x;
    int b = threadIdx.x;
    u32 v = g_hist[b * 256 + d];
    sc[b] = v;
    __syncthreads();
#pragma unroll
    for (int off = 1; off < 256; off <<= 1) {
        u32 t = (b >= off) ? sc[b - off] : 0u;
        __syncthreads();
        sc[b] += t;
        __syncthreads();
    }
    g_hist[b * 256 + d] = sc[b] - v;
    if (b == 255) g_digtot[d] = sc[255];
}

__global__ void radix_digbase_kernel() {
    __shared__ u32 sc[256];
    int d = threadIdx.x;
    u32 v = g_digtot[d];
    sc[d] = v;
    __syncthreads();
#pragma unroll
    for (int off = 1; off < 256; off <<= 1) {
        u32 t = (d >= off) ? sc[d - off] : 0u;
        __syncthreads();
        sc[d] += t;
        __syncthreads();
    }
    g_digbase[d] = sc[d] - v;
}

__global__ void radix_scatter_kernel(const u64* __restrict__ in, u64* __restrict__ out, int shift) {
    __shared__ u32 whist[8][256];
    int t = threadIdx.x, b = blockIdx.x;
    int lane = t & 31, wid = t >> 5;

#pragma unroll
    for (int i = 0; i < 8; i++) whist[i][t] = 0;
    __syncthreads();

    u64 key = in[b * 256 + t];
    u32 d = (u32)((key >> shift) & 0xFF);

    u32 mmask = __match_any_sync(0xffffffffu, d);
    u32 lrank = __popc(mmask & ((1u << lane) - 1u));
    if (lrank == 0) whist[wid][d] = __popc(mmask);
    __syncthreads();

    u32 rank = lrank;
#pragma unroll
    for (int w2 = 0; w2 < 8; w2++)
        if (w2 < wid) rank += whist[w2][d];

    out[g_digbase[d] + g_hist[b * 256 + d] + rank] = key;
}

// ---------------- gather + PE ------------------------------------------------
__global__ void gather_pe_kernel(const u64* __restrict__ keys,
                                 const int* __restrict__ coords,
                                 const float* __restrict__ feat,
                                 const float* __restrict__ pex,
                                 const float* __restrict__ pey,
                                 const float* __restrict__ pez,
                                 const float* __restrict__ pes,
                                 float* __restrict__ x,
                                 __half* __restrict__ x16) {
    int i = blockIdx.x;
    int t = threadIdx.x;
    int j = (int)(keys[i] & 0xFFFFu);
    int cx = coords[j * 4 + 1];
    int cy = coords[j * 4 + 2];
    int cz = coords[j * 4 + 3];
    float v = feat[(size_t)j * 256 + t]
            + pex[cx * 256 + t] + pey[cy * 256 + t]
            + pez[cz * 256 + t] + pes[256 + t];
    x[(size_t)i * 256 + t]   = v;
    x16[(size_t)i * 256 + t] = __float2half_rn(v);
}

// ---------------- shared mma helpers ----------------------------------------
__device__ __forceinline__ void cp_async16h(u32 saddr, const void* g) {
    asm volatile("cp.async.cg.shared.global [%0], [%1], 16;" :: "r"(saddr), "l"(g));
}
__device__ __forceinline__ void ldsm4(u32& r0, u32& r1, u32& r2, u32& r3, u32 addr) {
    asm volatile("ldmatrix.sync.aligned.m8n8.x4.shared.b16 {%0,%1,%2,%3}, [%4];"
                 : "=r"(r0), "=r"(r1), "=r"(r2), "=r"(r3) : "r"(addr));
}
__device__ __forceinline__ void mma16816(float* c, const u32* a, const u32* b) {
    asm volatile(
        "mma.sync.aligned.m16n8k16.row.col.f32.f16.f16.f32 "
        "{%0,%1,%2,%3}, {%4,%5,%6,%7}, {%8,%9}, {%0,%1,%2,%3};"
        : "+f"(c[0]), "+f"(c[1]), "+f"(c[2]), "+f"(c[3])
        : "r"(a[0]), "r"(a[1]), "r"(a[2]), "r"(a[3]), "r"(b[0]), "r"(b[1]));
}

// ============ GEMM A: 128x128x64, 3-stage, 128 threads, 64x64 warp tiles =====
#define G6_BM 128
#define G6_BN 128
#define G6_BK 64
#define G6_NSTAGE 3
#define G6_ASTAGE (G6_BM * G6_BK * 2)
#define G6_STAGE  (G6_ASTAGE * 2)
#define G6_SMEM   (G6_NSTAGE * G6_STAGE)

__global__ __launch_bounds__(128) void gemm_f16_kernel(
    const __half* __restrict__ A, const __half* __restrict__ B,
    const float* __restrict__ bias, __half* __restrict__ C16,
    int Nn, int K, int mode)
{
    extern __shared__ char smem_raw[];
    u32 sbase = (u32)__cvta_generic_to_shared(smem_raw);

    int tid  = threadIdx.x;
    int lane = tid & 31;
    int warp = tid >> 5;
    int wm = warp & 1;
    int wn = warp >> 1;
    int m0 = blockIdx.y * G6_BM;
    int n0 = blockIdx.x * G6_BN;

    const __half* Ag = A + (size_t)m0 * K;
    const __half* Bg = B + (size_t)n0 * K;

    float c[4][8][4];
#pragma unroll
    for (int i = 0; i < 4; i++)
#pragma unroll
        for (int j = 0; j < 8; j++)
#pragma unroll
            for (int k = 0; k < 4; k++) c[i][j][k] = 0.f;

    const int KT = K / G6_BK;

    auto load_stage = [&](int tile) {
        if (tile < KT) {
            int k0 = tile * G6_BK;
            u32 sa = sbase + (u32)(tile % G6_NSTAGE) * G6_STAGE;
            u32 sb = sa + G6_ASTAGE;
#pragma unroll
            for (int i = 0; i < 8; i++) {
                int q = tid + i * 128;
                int r = q >> 3, ch = q & 7;
                u32 off = (u32)(r * 8 + (ch ^ (r & 7))) * 16u;
                cp_async16h(sa + off, Ag + (size_t)r * K + k0 + ch * 8);
                cp_async16h(sb + off, Bg + (size_t)r * K + k0 + ch * 8);
            }
        }
        asm volatile("cp.async.commit_group;");
    };

    load_stage(0);
    load_stage(1);

    int idx  = lane >> 3;
    int lrow = lane & 7;
    int a_mo = (idx & 1) * 8;
    int a_kc = idx >> 1;
    int b_no = (idx >> 1) * 8;
    int b_kc = idx & 1;

    for (int kt = 0; kt < KT; kt++) {
        asm volatile("cp.async.wait_group 1;");
        __syncthreads();
        load_stage(kt + 2);

        u32 sa = sbase + (u32)(kt % G6_NSTAGE) * G6_STAGE;
        u32 sb = sa + G6_ASTAGE;

#pragma unroll
        for (int ks = 0; ks < 4; ks++) {
            u32 a[4][4];
#pragma unroll
            for (int mt = 0; mt < 4; mt++) {
                int r  = wm * 64 + mt * 16 + a_mo + lrow;
                int ch = ks * 2 + a_kc;
                ldsm4(a[mt][0], a[mt][1], a[mt][2], a[mt][3],
                      sa + (u32)(r * 8 + (ch ^ (r & 7))) * 16u);
            }
            u32 b[8][2];
#pragma unroll
            for (int nt2 = 0; nt2 < 4; nt2++) {
                int r  = wn * 64 + nt2 * 16 + b_no + lrow;
                int ch = ks * 2 + b_kc;
                u32 t0, t1, t2, t3;
                ldsm4(t0, t1, t2, t3, sb + (u32)(r * 8 + (ch ^ (r & 7))) * 16u);
                b[nt2 * 2][0] = t0; b[nt2 * 2][1] = t1;
                b[nt2 * 2 + 1][0] = t2; b[nt2 * 2 + 1][1] = t3;
            }
#pragma unroll
            for (int mt = 0; mt < 4; mt++)
#pragma unroll
                for (int nt = 0; nt < 8; nt++)
                    mma16816(c[mt][nt], a[mt], b[nt]);
        }
        __syncthreads();
    }

#pragma unroll
    for (int mt = 0; mt < 4; mt++) {
#pragma unroll
        for (int nt = 0; nt < 8; nt++) {
            int row = m0 + wm * 64 + mt * 16 + (lane >> 2);
            int col = n0 + wn * 64 + nt * 8 + (lane & 3) * 2;
            float2 bv = *(const float2*)(bias + col);
            float v0 = c[mt][nt][0] + bv.x;
            float v1 = c[mt][nt][1] + bv.y;
            float v2 = c[mt][nt][2] + bv.x;
            float v3 = c[mt][nt][3] + bv.y;
            if (mode == 2) {
                v0 = fmaxf(v0, 0.f); v1 = fmaxf(v1, 0.f);
                v2 = fmaxf(v2, 0.f); v3 = fmaxf(v3, 0.f);
            }
            *(__half2*)(C16 + (size_t)row * Nn + col) = __floats2half2_rn(v0, v1);
            *(__half2*)(C16 + (size_t)(row + 8) * Nn + col) = __floats2half2_rn(v2, v3);
        }
    }
}

// ============ GEMM B: 128x256x64, 3-stage, fused residual + LayerNorm ========
// register-capped at 1 CTA/SM anyway -> 3-stage smem (147KB) is free occupancy-
// wise and deepens prefetch for the DRAM-heavy FF2 (K=2048).
#define GL_BM 128
#define GL_BN 256
#define GL_BK 64
#define GL_NSTAGE 3
#define GL_ASTAGE (GL_BM * GL_BK * 2)
#define GL_BSTAGE (GL_BN * GL_BK * 2)
#define GL_STAGE  (GL_ASTAGE + GL_BSTAGE)
#define GL_SMEM   (GL_NSTAGE * GL_STAGE)   // 147456

__global__ __launch_bounds__(256) void gemm_ln_kernel(
    const __half* __restrict__ A, const __half* __restrict__ B,
    const float* __restrict__ bias,
    __half* __restrict__ C16, float* __restrict__ C32,
    const float* __restrict__ resid,
    const float* __restrict__ gamma, const float* __restrict__ beta,
    int K)
{
    extern __shared__ char smem_raw[];
    u32 sbase = (u32)__cvta_generic_to_shared(smem_raw);

    int tid  = threadIdx.x;
    int lane = tid & 31;
    int warp = tid >> 5;
    int wm = warp & 1;
    int wn = warp >> 1;
    int m0 = blockIdx.y * GL_BM;

    const __half* Ag = A + (size_t)m0 * K;
    const __half* Bg = B;

    float c[4][8][4];
#pragma unroll
    for (int i = 0; i < 4; i++)
#pragma unroll
        for (int j = 0; j < 8; j++)
#pragma unroll
            for (int k = 0; k < 4; k++) c[i][j][k] = 0.f;

    const int KT = K / GL_BK;

    auto load_stage = [&](int tile) {
        if (tile < KT) {
            int k0 = tile * GL_BK;
            u32 sa = sbase + (u32)(tile % GL_NSTAGE) * GL_STAGE;
            u32 sb = sa + GL_ASTAGE;
#pragma unroll
            for (int i = 0; i < 4; i++) {
                int q = tid + i * 256;
                int r = q >> 3, ch = q & 7;
                u32 off = (u32)(r * 8 + (ch ^ (r & 7))) * 16u;
                cp_async16h(sa + off, Ag + (size_t)r * K + k0 + ch * 8);
            }
#pragma unroll
            for (int i = 0; i < 8; i++) {
                int q = tid + i * 256;
                int r = q >> 3, ch = q & 7;
                u32 off = (u32)(r * 8 + (ch ^ (r & 7))) * 16u;
                cp_async16h(sb + off, Bg + (size_t)r * K + k0 + ch * 8);
            }
        }
        asm volatile("cp.async.commit_group;");
    };

    load_stage(0);
    load_stage(1);

    int idx  = lane >> 3;
    int lrow = lane & 7;
    int a_mo = (idx & 1) * 8;
    int a_kc = idx >> 1;
    int b_no = (idx >> 1) * 8;
    int b_kc = idx & 1;

    for (int kt = 0; kt < KT; kt++) {
        asm volatile("cp.async.wait_group 1;");
        __syncthreads();
        load_stage(kt + 2);

        u32 sa = sbase + (u32)(kt % GL_NSTAGE) * GL_STAGE;
        u32 sb = sa + GL_ASTAGE;

#pragma unroll
        for (int ks = 0; ks < 4; ks++) {
            u32 a[4][4];
#pragma unroll
            for (int mt = 0; mt < 4; mt++) {
                int r  = wm * 64 + mt * 16 + a_mo + lrow;
                int ch = ks * 2 + a_kc;
                ldsm4(a[mt][0], a[mt][1], a[mt][2], a[mt][3],
                      sa + (u32)(r * 8 + (ch ^ (r & 7))) * 16u);
            }
            u32 b[8][2];
#pragma unroll
            for (int nt2 = 0; nt2 < 4; nt2++) {
                int r  = wn * 64 + nt2 * 16 + b_no + lrow;
                int ch = ks * 2 + b_kc;
                u32 t0, t1, t2, t3;
                ldsm4(t0, t1, t2, t3, sb + (u32)(r * 8 + (ch ^ (r & 7))) * 16u);
                b[nt2 * 2][0] = t0; b[nt2 * 2][1] = t1;
                b[nt2 * 2 + 1][0] = t2; b[nt2 * 2 + 1][1] = t3;
            }
#pragma unroll
            for (int mt = 0; mt < 4; mt++)
#pragma unroll
                for (int nt = 0; nt < 8; nt++)
                    mma16816(c[mt][nt], a[mt], b[nt]);
        }
        __syncthreads();
    }

    asm volatile("cp.async.wait_group 0;");
    __syncthreads();

    float2 bv[8];
#pragma unroll
    for (int nt = 0; nt < 8; nt++)
        bv[nt] = *(const float2*)(bias + wn * 64 + nt * 8 + (lane & 3) * 2);

    float* red = (float*)smem_raw;

#pragma unroll
    for (int mt = 0; mt < 4; mt++) {
#pragma unroll
        for (int rh = 0; rh < 2; rh++) {
            int rowl = wm * 64 + mt * 16 + (lane >> 2) + rh * 8;
            const float* rrow = resid + (size_t)(m0 + rowl) * 256 + wn * 64 + (lane & 3) * 2;
            float s = 0.f, s2 = 0.f;
#pragma unroll
            for (int nt = 0; nt < 8; nt++) {
                float2 rv = *(const float2*)(rrow + nt * 8);
                float v0 = c[mt][nt][rh * 2]     + bv[nt].x + rv.x;
                float v1 = c[mt][nt][rh * 2 + 1] + bv[nt].y + rv.y;
                c[mt][nt][rh * 2]     = v0;
                c[mt][nt][rh * 2 + 1] = v1;
                s += v0 + v1;
                s2 = fmaf(v0, v0, s2);
                s2 = fmaf(v1, v1, s2);
            }
            s  += __shfl_xor_sync(0xffffffffu, s, 1);
            s  += __shfl_xor_sync(0xffffffffu, s, 2);
            s2 += __shfl_xor_sync(0xffffffffu, s2, 1);
            s2 += __shfl_xor_sync(0xffffffffu, s2, 2);
            if ((lane & 3) == 0) {
                red[rowl * 8 + wn * 2]     = s;
                red[rowl * 8 + wn * 2 + 1] = s2;
            }
        }
    }
    __syncthreads();

    float2 gv[8], bev[8];
#pragma unroll
    for (int nt = 0; nt < 8; nt++) {
        int col = wn * 64 + nt * 8 + (lane & 3) * 2;
        gv[nt]  = *(const float2*)(gamma + col);
        bev[nt] = *(const float2*)(beta + col);
    }

#pragma unroll
    for (int mt = 0; mt < 4; mt++) {
#pragma unroll
        for (int rh = 0; rh < 2; rh++) {
            int rowl = wm * 64 + mt * 16 + (lane >> 2) + rh * 8;
            float s  = red[rowl * 8 + 0] + red[rowl * 8 + 2] + red[rowl * 8 + 4] + red[rowl * 8 + 6];
            float s2 = red[rowl * 8 + 1] + red[rowl * 8 + 3] + red[rowl * 8 + 5] + red[rowl * 8 + 7];
            float mean = s * (1.f / 256.f);
            float var  = s2 * (1.f / 256.f) - mean * mean;
            float rstd = rsqrtf(var + 1e-5f);
            int row = m0 + rowl;
            float*  o32 = C32 + (size_t)row * 256 + wn * 64 + (lane & 3) * 2;
            __half* o16 = C16 + (size_t)row * 256 + wn * 64 + (lane & 3) * 2;
#pragma unroll
            for (int nt = 0; nt < 8; nt++) {
                float v0 = (c[mt][nt][rh * 2]     - mean) * rstd * gv[nt].x + bev[nt].x;
                float v1 = (c[mt][nt][rh * 2 + 1] - mean) * rstd * gv[nt].y + bev[nt].y;
                float2 o = {v0, v1};
                *(float2*)(o32 + nt * 8) = o;
                *(__half2*)(o16 + nt * 8) = __floats2half2_rn(v0, v1);
            }
        }
    }
}

// ---------------- flash attention: mma + f16x2 exp, no running max -----------
#define QK_STRB 80
#define VT_STRB 272
__device__ __forceinline__ u32 h2ex2(u32 x) {
    u32 r;
    asm volatile("ex2.approx.f16x2 %0, %1;" : "=r"(r) : "r"(x));
    return r;
}
__device__ __forceinline__ u32 packh2(float a, float b) {
    __half2 h = __floats2half2_rn(a, b);
    return *(u32*)&h;
}

__global__ __launch_bounds__(128) void attn_mma_kernel(const __half* __restrict__ qkv,
                                                       __half* __restrict__ att16) {
    __shared__ __align__(16) __half Qs[128 * 40];
    __shared__ __align__(16) __half Ks[128 * 40];
    __shared__ __align__(16) __half Vt[32 * 136];

    int w = blockIdx.x;
    int h = blockIdx.y;
    int p = threadIdx.x;
    int lane = p & 31;
    int warp = p >> 5;

    {
        const __half* base = qkv + ((size_t)w * WS + p) * 768 + h * 32;
        const uint4* q4 = (const uint4*)base;
        const uint4* k4 = (const uint4*)(base + 256);
        const uint4* v4 = (const uint4*)(base + 512);
        uint4* qd = (uint4*)(Qs + p * 40);
        uint4* kd = (uint4*)(Ks + p * 40);
#pragma unroll
        for (int c = 0; c < 4; c++) { qd[c] = q4[c]; kd[c] = k4[c]; }
        union { uint4 u[4]; __half hh[32]; } vv;
#pragma unroll
        for (int c = 0; c < 4; c++) vv.u[c] = v4[c];
#pragma unroll
        for (int d = 0; d < 32; d++) Vt[d * 136 + p] = vv.hh[d];
    }
    __syncthreads();

    u32 qsb = (u32)__cvta_generic_to_shared(Qs);
    u32 ksb = (u32)__cvta_generic_to_shared(Ks);
    u32 vtb = (u32)__cvta_generic_to_shared(Vt);

    int idx  = lane >> 3;
    int lrow = lane & 7;
    int a_mo = (idx & 1) * 8;
    int a_kc = idx >> 1;
    int b_no = (idx >> 1) * 8;
    int b_kc = idx & 1;
    int m_base = warp * 32;

    const float scale = 0.2550540263f;  // log2(e)/sqrt(32)

    float lrow_s[2][2];
    float o[2][4][4];
#pragma unroll
    for (int t = 0; t < 2; t++)
#pragma unroll
        for (int rh = 0; rh < 2; rh++) lrow_s[t][rh] = 0.f;
#pragma unroll
    for (int t = 0; t < 2; t++)
#pragma unroll
        for (int n = 0; n < 4; n++)
#pragma unroll
            for (int k = 0; k < 4; k++) o[t][n][k] = 0.f;

#pragma unroll
    for (int chunk = 0; chunk < 2; chunk++) {
        int n0c = chunk * 64;

        float s[2][8][4];
#pragma unroll
        for (int t = 0; t < 2; t++)
#pragma unroll
            for (int n = 0; n < 8; n++)
#pragma unroll
                for (int k = 0; k < 4; k++) s[t][n][k] = 0.f;

#pragma unroll
        for (int ks = 0; ks < 2; ks++) {
            u32 a[2][4];
#pragma unroll
            for (int t = 0; t < 2; t++) {
                int r  = m_base + t * 16 + a_mo + lrow;
                int ch = ks * 2 + a_kc;
                ldsm4(a[t][0], a[t][1], a[t][2], a[t][3],
                      qsb + (u32)(r * QK_STRB + ch * 16));
            }
            u32 b[8][2];
#pragma unroll
            for (int np = 0; np < 4; np++) {
                int r  = n0c + np * 16 + b_no + lrow;
                int ch = ks * 2 + b_kc;
                u32 t0, t1, t2, t3;
                ldsm4(t0, t1, t2, t3, ksb + (u32)(r * QK_STRB + ch * 16));
                b[np * 2][0] = t0; b[np * 2][1] = t1;
                b[np * 2 + 1][0] = t2; b[np * 2 + 1][1] = t3;
            }
#pragma unroll
            for (int t = 0; t < 2; t++)
#pragma unroll
                for (int n = 0; n < 8; n++)
                    mma16816(s[t][n], a[t], b[n]);
        }

        u32 pf_lo[2][8], pf_hi[2][8];
#pragma unroll
        for (int t = 0; t < 2; t++) {
#pragma unroll
            for (int rh = 0; rh < 2; rh++) {
                float lsum = 0.f;
#pragma unroll
                for (int n = 0; n < 8; n++) {
                    float v0 = s[t][n][rh * 2]     * scale;
                    float v1 = s[t][n][rh * 2 + 1] * scale;
                    u32 pp = h2ex2(packh2(v0, v1));
                    if (rh == 0) pf_lo[t][n] = pp; else pf_hi[t][n] = pp;
                    __half2 ph = *(__half2*)&pp;
                    float2 pfv = __half22float2(ph);
                    lsum += pfv.x + pfv.y;
                }
                lrow_s[t][rh] += lsum;
            }
        }

#pragma unroll
        for (int ks2 = 0; ks2 < 4; ks2++) {
            u32 b[4][2];
#pragma unroll
            for (int np = 0; np < 2; np++) {
                int r = np * 16 + b_no + lrow;
                int kh = n0c + ks2 * 16 + b_kc * 8;
                u32 t0, t1, t2, t3;
                ldsm4(t0, t1, t2, t3, vtb + (u32)(r * VT_STRB + kh * 2));
                b[np * 2][0] = t0; b[np * 2][1] = t1;
                b[np * 2 + 1][0] = t2; b[np * 2 + 1][1] = t3;
            }
#pragma unroll
            for (int t = 0; t < 2; t++) {
                u32 a[4];
                a[0] = pf_lo[t][ks2 * 2];
                a[1] = pf_hi[t][ks2 * 2];
                a[2] = pf_lo[t][ks2 * 2 + 1];
                a[3] = pf_hi[t][ks2 * 2 + 1];
#pragma unroll
                for (int n = 0; n < 4; n++)
                    mma16816(o[t][n], a, b[n]);
            }
        }
    }

#pragma unroll
    for (int t = 0; t < 2; t++) {
#pragma unroll
        for (int rh = 0; rh < 2; rh++) {
            float lr = lrow_s[t][rh];
            lr += __shfl_xor_sync(0xffffffffu, lr, 1);
            lr += __shfl_xor_sync(0xffffffffu, lr, 2);
            float inv = 1.f / lr;
            int row = w * WS + m_base + t * 16 + (lane >> 2) + rh * 8;
            __half* outp = att16 + (size_t)row * 256 + h * 32 + (lane & 3) * 2;
#pragma unroll
            for (int n = 0; n < 4; n++) {
                *(__half2*)(outp + n * 8) =
                    __floats2half2_rn(o[t][n][rh * 2] * inv, o[t][n][rh * 2 + 1] * inv);
            }
        }
    }
}

// ---------------- launch ------------------------------------------------------
extern "C" void kernel_launch(void* const* d_in, const int* in_sizes, int n_in,
                              void* d_out, int out_size) {
    const int*   coords = (const int*)d_in[0];
    const float* feat   = (const float*)d_in[1];
    const float* pex    = (const float*)d_in[2];
    const float* pey    = (const float*)d_in[3];
    const float* pez    = (const float*)d_in[4];
    const float* pes    = (const float*)d_in[5];
    const float* Wqkv   = (const float*)d_in[6];
    const float* bqkv   = (const float*)d_in[7];
    const float* Wo     = (const float*)d_in[8];
    const float* bo     = (const float*)d_in[9];
    const float* W1     = (const float*)d_in[10];
    const float* b1     = (const float*)d_in[11];
    const float* W2     = (const float*)d_in[12];
    const float* b2     = (const float*)d_in[13];
    const float* g1     = (const float*)d_in[14];
    const float* be1    = (const float*)d_in[15];
    const float* g2     = (const float*)d_in[16];
    const float* be2    = (const float*)d_in[17];

    u64 *ka, *kb;
    float *xp;
    __half *qkv16p, *x16p, *att16p, *ff16p, *w16p;
    cudaGetSymbolAddress((void**)&ka,     g_keysA);
    cudaGetSymbolAddress((void**)&kb,     g_keysB);
    cudaGetSymbolAddress((void**)&xp,     g_x);
    cudaGetSymbolAddress((void**)&qkv16p, g_qkv16);
    cudaGetSymbolAddress((void**)&x16p,   g_x16);
    cudaGetSymbolAddress((void**)&att16p, g_att16);
    cudaGetSymbolAddress((void**)&ff16p,  g_ff16);
    cudaGetSymbolAddress((void**)&w16p,   g_w16);

    static int attr_done = 0;
    if (!attr_done) {
        cudaFuncSetAttribute(gemm_f16_kernel,
                             cudaFuncAttributeMaxDynamicSharedMemorySize, G6_SMEM);
        cudaFuncSetAttribute(gemm_ln_kernel,
                             cudaFuncAttributeMaxDynamicSharedMemorySize, GL_SMEM);
        attr_done = 1;
    }

    // 0) weights -> fp16
    cvt_all_kernel<<<5242880 / 256, 256>>>(Wqkv, Wo, W1, W2, w16p);

    // 1) sort
    build_keys_kernel<<<256, 256>>>(coords, ka);
    int shifts[3] = {16, 24, 32};
    u64* src = ka;
    u64* dst = kb;
    for (int p = 0; p < 3; p++) {
        radix_hist_kernel<<<256, 256>>>(src, shifts[p]);
        radix_colscan_kernel<<<256, 256>>>();
        radix_digbase_kernel<<<1, 256>>>();
        radix_scatter_kernel<<<256, 256>>>(src, dst, shifts[p]);
        u64* t = src; src = dst; dst = t;
    }

    // 2) gather + PE
    gather_pe_kernel<<<N_PTS, 256>>>(src, coords, feat, pex, pey, pez, pes, xp, x16p);

    // 3) layers
    for (int l = 0; l < NLAYER; l++) {
        const __half* wqkv = w16p + WOFF_QKV + (size_t)l * 768 * 256;
        const float*  bq   = bqkv + (size_t)l * 768;
        const __half* wo   = w16p + WOFF_O + (size_t)l * 256 * 256;
        const float*  bo_l = bo   + (size_t)l * 256;
        const __half* w1   = w16p + WOFF_1 + (size_t)l * 2048 * 256;
        const float*  b1_l = b1   + (size_t)l * 2048;
        const __half* w2   = w16p + WOFF_2 + (size_t)l * 256 * 2048;
        const float*  b2_l = b2   + (size_t)l * 256;

        gemm_f16_kernel<<<dim3(768 / G6_BN, N_PTS / G6_BM), 128, G6_SMEM>>>(
            x16p, wqkv, bq, qkv16p, 768, 256, 1);

        attn_mma_kernel<<<dim3(N_PTS / WS, NH), 128>>>(qkv16p, att16p);

        gemm_ln_kernel<<<dim3(1, N_PTS / GL_BM), 256, GL_SMEM>>>(
            att16p, wo, bo_l, x16p, xp, xp, g1 + l * 256, be1 + l * 256, 256);

        gemm_f16_kernel<<<dim3(2048 / G6_BN, N_PTS / G6_BM), 128, G6_SMEM>>>(
            x16p, w1, b1_l, ff16p, 2048, 256, 2);

        float* outp = (l == NLAYER - 1) ? (float*)d_out : xp;
        gemm_ln_kernel<<<dim3(1, N_PTS / GL_BM), 256, GL_SMEM>>>(
            ff16p, w2, b2_l, x16p, outp, xp, g2 + l * 256, be2 + l * 256, 2048);
    }
}